// round 1
// baseline (speedup 1.0000x reference)
#include <cuda_runtime.h>
#include <math.h>

// Problem dims
#define B_   256
#define T_   200
#define E_   512
#define H_   8
#define DH_  64
#define FF_  2048
#define BT_  (B_*T_)

#define NEGV (-4294967295.0f)

// ---------------------------------------------------------------------------
// Scratch: single device-global array (no allocations anywhere).
//   qin  : BT*E
//   kin  : BT*E
//   Q    : BT*E
//   K    : BT*E
//   V    : BT*E
//   ctx  : BT*E   (attention out + residual)
//   o2   : BT*E   (ffn out + residual)
//   hid  : BT*FF  (ffn hidden)
// total = 7*BT*E + BT*FF floats = 288,358,400 floats (~1.15 GB)
// ---------------------------------------------------------------------------
__device__ float g_scratch[(size_t)7 * BT_ * E_ + (size_t)BT_ * FF_];

// ---------------------------------------------------------------------------
// Kernel 1: positional encoding add:  q_in = q + pos_q*sqrt(E), same for k.
// ---------------------------------------------------------------------------
__global__ void add_pos_kernel(const float4* __restrict__ q,
                               const float4* __restrict__ k,
                               const float4* __restrict__ pq,
                               const float4* __restrict__ pk,
                               float4* __restrict__ qin,
                               float4* __restrict__ kin) {
    int i  = blockIdx.x * 256 + threadIdx.x;        // over BT*E/4
    int pi = i % (T_ * E_ / 4);
    const float s = 22.62741699796952f;             // sqrt(512)
    float4 a = q[i], p = pq[pi];
    float4 r;
    r.x = a.x + p.x * s; r.y = a.y + p.y * s;
    r.z = a.z + p.z * s; r.w = a.w + p.w * s;
    qin[i] = r;
    a = k[i]; p = pk[pi];
    r.x = a.x + p.x * s; r.y = a.y + p.y * s;
    r.z = a.z + p.z * s; r.w = a.w + p.w * s;
    kin[i] = r;
}

// ---------------------------------------------------------------------------
// Kernel 2: fp32 SGEMM  C[M,N] = A[M,K] @ Bw[K,N]  (+C0) (ReLU)
// BM=BN=128, BK=8, 256 threads, 8x8 micro-tile per thread.
// All dims assumed divisible (M%128==0, N%128==0, K%8==0) — true here.
// ---------------------------------------------------------------------------
template <bool RELU, bool ADD>
__global__ void __launch_bounds__(256)
sgemm_kernel(const float* __restrict__ A, const float* __restrict__ Bw,
             const float* __restrict__ C0, float* __restrict__ C,
             int M, int N, int K) {
    __shared__ float As[8][128];
    __shared__ float Bs[8][128];

    const int tid  = threadIdx.x;
    const int row0 = blockIdx.y * 128;
    const int col0 = blockIdx.x * 128;

    const int arow = tid >> 1;            // 0..127
    const int acol = (tid & 1) * 4;       // 0 or 4
    const int brow = tid >> 5;            // 0..7
    const int bcol = (tid & 31) * 4;      // 0..124

    const int trow = (tid >> 4) * 8;      // 0..120
    const int tcol = (tid & 15) * 8;      // 0..120

    float acc[8][8];
#pragma unroll
    for (int i = 0; i < 8; i++)
#pragma unroll
        for (int j = 0; j < 8; j++) acc[i][j] = 0.f;

    for (int k0 = 0; k0 < K; k0 += 8) {
        float4 av = *(const float4*)&A[(size_t)(row0 + arow) * K + k0 + acol];
        float4 bv = *(const float4*)&Bw[(size_t)(k0 + brow) * N + col0 + bcol];
        As[acol + 0][arow] = av.x;
        As[acol + 1][arow] = av.y;
        As[acol + 2][arow] = av.z;
        As[acol + 3][arow] = av.w;
        *(float4*)&Bs[brow][bcol] = bv;
        __syncthreads();

#pragma unroll
        for (int k = 0; k < 8; k++) {
            float4 a0 = *(const float4*)&As[k][trow];
            float4 a1 = *(const float4*)&As[k][trow + 4];
            float4 b0 = *(const float4*)&Bs[k][tcol];
            float4 b1 = *(const float4*)&Bs[k][tcol + 4];
            float ar[8] = {a0.x, a0.y, a0.z, a0.w, a1.x, a1.y, a1.z, a1.w};
            float br[8] = {b0.x, b0.y, b0.z, b0.w, b1.x, b1.y, b1.z, b1.w};
#pragma unroll
            for (int i = 0; i < 8; i++)
#pragma unroll
                for (int j = 0; j < 8; j++) acc[i][j] += ar[i] * br[j];
        }
        __syncthreads();
    }

#pragma unroll
    for (int i = 0; i < 8; i++) {
        size_t rbase = (size_t)(row0 + trow + i) * N + col0 + tcol;
#pragma unroll
        for (int j = 0; j < 8; j += 4) {
            float4 v;
            v.x = acc[i][j + 0]; v.y = acc[i][j + 1];
            v.z = acc[i][j + 2]; v.w = acc[i][j + 3];
            if (ADD) {
                float4 c = *(const float4*)&C0[rbase + j];
                v.x += c.x; v.y += c.y; v.z += c.z; v.w += c.w;
            }
            if (RELU) {
                v.x = fmaxf(v.x, 0.f); v.y = fmaxf(v.y, 0.f);
                v.z = fmaxf(v.z, 0.f); v.w = fmaxf(v.w, 0.f);
            }
            *(float4*)&C[rbase + j] = v;
        }
    }
}

// ---------------------------------------------------------------------------
// Kernel 3: fused masked attention per (b,h).
// K,V head tiles resident in smem; one warp per query row; scores in smem;
// exact reference semantics: NEG mask for invalid keys + diagonal, subtract
// rowmax, softmax (all-masked rows -> uniform), q_mask + residual in epilogue.
// ---------------------------------------------------------------------------
__global__ void __launch_bounds__(256)
attn_kernel(const int* __restrict__ qlen, const int* __restrict__ klen,
            const float* __restrict__ Q, const float* __restrict__ Kt,
            const float* __restrict__ V, const float* __restrict__ qin,
            float* __restrict__ ctx) {
    extern __shared__ float sm[];
    float* Ks = sm;                    // 200*65
    float* Vs = Ks + T_ * 65;          // 200*65
    float* Sc = Vs + T_ * 65;          // 8*200
    float* Qs = Sc + 8 * T_;           // 8*64

    const int h = blockIdx.x, b = blockIdx.y;
    const int tid = threadIdx.x, w = tid >> 5, lane = tid & 31;
    const int kl = klen[b], ql = qlen[b];

    // load K,V head tiles (padded rows: stride 65 -> conflict-free)
    for (int i = tid; i < T_ * DH_; i += 256) {
        int t = i >> 6, d = i & 63;
        size_t gi = (size_t)(b * T_ + t) * E_ + h * DH_ + d;
        Ks[t * 65 + d] = Kt[gi];
        Vs[t * 65 + d] = V[gi];
    }
    __syncthreads();

    const float inv_sqrt_dh = 0.125f;

    for (int q = w; q < T_; q += 8) {
        // load Q row into smem (per-warp)
        size_t qbase = (size_t)(b * T_ + q) * E_ + h * DH_;
        Qs[w * 64 + lane]      = Q[qbase + lane];
        Qs[w * 64 + lane + 32] = Q[qbase + lane + 32];
        __syncwarp();

        // scores + max
        float smax = -INFINITY;
#pragma unroll
        for (int kb = 0; kb < 7; kb++) {
            int kk = kb * 32 + lane;
            if (kk < T_) {
                float dot = 0.f;
#pragma unroll
                for (int d = 0; d < DH_; d++)
                    dot += Qs[w * 64 + d] * Ks[kk * 65 + d];
                float s = (kk < kl && kk != q) ? dot * inv_sqrt_dh : NEGV;
                Sc[w * 200 + kk] = s;
                smax = fmaxf(smax, s);
            }
        }
#pragma unroll
        for (int off = 16; off; off >>= 1)
            smax = fmaxf(smax, __shfl_xor_sync(0xffffffff, smax, off));

        // exp + sum
        float ssum = 0.f;
#pragma unroll
        for (int kb = 0; kb < 7; kb++) {
            int kk = kb * 32 + lane;
            if (kk < T_) {
                float e = expf(Sc[w * 200 + kk] - smax);
                Sc[w * 200 + kk] = e;
                ssum += e;
            }
        }
#pragma unroll
        for (int off = 16; off; off >>= 1)
            ssum += __shfl_xor_sync(0xffffffff, ssum, off);

        float scale = (q < ql) ? (1.0f / ssum) : 0.0f;  // q_mask folded in
        __syncwarp();

        // attn @ V  (lane owns output dims lane, lane+32)
        float acc0 = 0.f, acc1 = 0.f;
        for (int kk = 0; kk < T_; kk++) {
            float p = Sc[w * 200 + kk];
            acc0 += p * Vs[kk * 65 + lane];
            acc1 += p * Vs[kk * 65 + lane + 32];
        }
        // residual with q_in
        ctx[qbase + lane]      = acc0 * scale + qin[qbase + lane];
        ctx[qbase + lane + 32] = acc1 * scale + qin[qbase + lane + 32];
    }
}

// ---------------------------------------------------------------------------
// Kernel 4: mean over T -> (B,1,E)
// ---------------------------------------------------------------------------
__global__ void mean_kernel(const float* __restrict__ o2, float* __restrict__ out) {
    int b = blockIdx.x, e = threadIdx.x;   // 256 blocks x 512 threads
    float s = 0.f;
    for (int t = 0; t < T_; t++)
        s += o2[(size_t)(b * T_ + t) * E_ + e];
    out[b * E_ + e] = s * (1.0f / T_);
}

// ---------------------------------------------------------------------------
// Launch
// ---------------------------------------------------------------------------
extern "C" void kernel_launch(void* const* d_in, const int* in_sizes, int n_in,
                              void* d_out, int out_size) {
    const float* queries = (const float*)d_in[0];
    const float* keys    = (const float*)d_in[1];
    const int*   qlen    = (const int*)d_in[2];
    const int*   klen    = (const int*)d_in[3];
    const float* pos_q   = (const float*)d_in[4];
    const float* pos_k   = (const float*)d_in[5];
    const float* W_Q     = (const float*)d_in[6];
    const float* W_K     = (const float*)d_in[7];
    const float* W_V     = (const float*)d_in[8];
    const float* fw1     = (const float*)d_in[9];
    const float* fw2     = (const float*)d_in[10];
    float*       out     = (float*)d_out;

    float* base = nullptr;
    cudaGetSymbolAddress((void**)&base, g_scratch);
    const size_t BTE = (size_t)BT_ * E_;
    float* qin = base;
    float* kin = base + 1 * BTE;
    float* Qp  = base + 2 * BTE;
    float* Kp  = base + 3 * BTE;
    float* Vp  = base + 4 * BTE;
    float* ctx = base + 5 * BTE;
    float* o2  = base + 6 * BTE;
    float* hid = base + 7 * BTE;

    // 1. positional encoding
    add_pos_kernel<<<(BT_ * E_ / 4) / 256, 256>>>(
        (const float4*)queries, (const float4*)keys,
        (const float4*)pos_q, (const float4*)pos_k,
        (float4*)qin, (float4*)kin);

    // 2-4. QKV projections
    dim3 gproj(E_ / 128, BT_ / 128);
    sgemm_kernel<false, false><<<gproj, 256>>>(qin, W_Q, nullptr, Qp, BT_, E_, E_);
    sgemm_kernel<false, false><<<gproj, 256>>>(kin, W_K, nullptr, Kp, BT_, E_, E_);
    sgemm_kernel<false, false><<<gproj, 256>>>(kin, W_V, nullptr, Vp, BT_, E_, E_);

    // 5. fused attention (+ residual)
    const int SMEM = (2 * T_ * 65 + 8 * T_ + 8 * 64) * (int)sizeof(float); // 112448 B
    cudaFuncSetAttribute(attn_kernel, cudaFuncAttributeMaxDynamicSharedMemorySize, SMEM);
    attn_kernel<<<dim3(H_, B_), 256, SMEM>>>(qlen, klen, Qp, Kp, Vp, qin, ctx);

    // 6. FFN up + ReLU
    sgemm_kernel<true, false><<<dim3(FF_ / 128, BT_ / 128), 256>>>(
        ctx, fw1, nullptr, hid, BT_, FF_, E_);

    // 7. FFN down + residual
    sgemm_kernel<false, true><<<dim3(E_ / 128, BT_ / 128), 256>>>(
        hid, fw2, ctx, o2, BT_, E_, FF_);

    // 8. mean over time
    mean_kernel<<<B_, E_>>>(o2, out);
}

// round 3
// speedup vs baseline: 1.6260x; 1.6260x over previous
#include <cuda_runtime.h>
#include <cuda_fp16.h>
#include <math.h>
#include <stdint.h>

// Problem dims
#define B_   256
#define T_   200
#define E_   512
#define H_   8
#define DH_  64
#define FF_  2048
#define BT_  (B_*T_)

#define NEGV (-4294967295.0f)

// ---------------------------------------------------------------------------
// GEMM config: 128x128 CTA tile, BK=32, 8 warps (2x4), warp tile 64x32.
// smem planes of halfs with 40-half (80B) row pitch -> conflict-free frag LDS.
// ---------------------------------------------------------------------------
#define GBM 128
#define GBN 128
#define GBK 32
#define PADH 40
#define PLANE_B (GBM * PADH * 2)     // 10240 bytes per plane
#define STAGE_B (4 * PLANE_B)        // Ahi, Alo, Bhi, Blo = 40960 bytes
#define GEMM_DSMEM (2 * STAGE_B)     // 81920 bytes

__device__ __forceinline__ void mma16816(float* c, const uint32_t* a, const uint32_t* b) {
    asm volatile(
        "mma.sync.aligned.m16n8k16.row.col.f32.f16.f16.f32 "
        "{%0,%1,%2,%3}, {%4,%5,%6,%7}, {%8,%9}, {%0,%1,%2,%3};"
        : "+f"(c[0]), "+f"(c[1]), "+f"(c[2]), "+f"(c[3])
        : "r"(a[0]), "r"(a[1]), "r"(a[2]), "r"(a[3]), "r"(b[0]), "r"(b[1]));
}

__device__ __forceinline__ void split2(float x, float y, uint32_t& hi, uint32_t& lo) {
    __half hx = __float2half_rn(x);
    __half hy = __float2half_rn(y);
    __half lx = __float2half_rn(x - __half2float(hx));
    __half ly = __float2half_rn(y - __half2float(hy));
    hi = (uint32_t)__half_as_ushort(hx) | ((uint32_t)__half_as_ushort(hy) << 16);
    lo = (uint32_t)__half_as_ushort(lx) | ((uint32_t)__half_as_ushort(ly) << 16);
}

// C[M,N] = A[M,K] @ Bt[N,K]^T  (+C0) (ReLU), fp16-split 3-MMA for fp32 accuracy
template <bool RELU, bool ADD>
__global__ void __launch_bounds__(256)
hgemm_kernel(const float* __restrict__ A, const float* __restrict__ Bt,
             const float* __restrict__ C0, float* __restrict__ C,
             int M, int N, int K) {
    extern __shared__ char smem[];

    const int tid = threadIdx.x;
    const int wid = tid >> 5, lane = tid & 31;
    const int m0 = blockIdx.y * GBM;
    const int n0 = blockIdx.x * GBN;
    const int wm = (wid >> 2) * 64;      // warp row offset: 0 or 64
    const int wn = (wid & 3) * 32;       // warp col offset: 0,32,64,96
    const int g = lane >> 2, t = lane & 3;

    float acc[4][4][4];
#pragma unroll
    for (int i = 0; i < 4; i++)
#pragma unroll
        for (int j = 0; j < 4; j++)
#pragma unroll
            for (int k = 0; k < 4; k++) acc[i][j][k] = 0.f;

    const int nt = K / GBK;
    float4 la[4], lb[4];

    // per-thread tile coords: f4 = tid + j*256; row = f4>>3, c4 = f4&7
    auto LDG = [&](int k0) {
#pragma unroll
        for (int j = 0; j < 4; j++) {
            int f4 = tid + j * 256;
            int r = f4 >> 3, c4 = f4 & 7;
            la[j] = *(const float4*)(A + (size_t)(m0 + r) * K + k0 + c4 * 4);
            lb[j] = *(const float4*)(Bt + (size_t)(n0 + r) * K + k0 + c4 * 4);
        }
    };
    auto STS = [&](int s) {
        char* ahi = smem + s * STAGE_B;
        char* alo = ahi + PLANE_B;
        char* bhi = alo + PLANE_B;
        char* blo = bhi + PLANE_B;
#pragma unroll
        for (int j = 0; j < 4; j++) {
            int f4 = tid + j * 256;
            int r = f4 >> 3, c4 = f4 & 7;
            uint32_t off = r * (PADH * 2) + c4 * 8;
            uint32_t h01, l01, h23, l23;
            split2(la[j].x, la[j].y, h01, l01);
            split2(la[j].z, la[j].w, h23, l23);
            *(uint2*)(ahi + off) = make_uint2(h01, h23);
            *(uint2*)(alo + off) = make_uint2(l01, l23);
            split2(lb[j].x, lb[j].y, h01, l01);
            split2(lb[j].z, lb[j].w, h23, l23);
            *(uint2*)(bhi + off) = make_uint2(h01, h23);
            *(uint2*)(blo + off) = make_uint2(l01, l23);
        }
    };

    LDG(0);
    STS(0);

    for (int it = 0; it < nt; it++) {
        __syncthreads();
        if (it + 1 < nt) LDG((it + 1) * GBK);

        const char* ahi = smem + (it & 1) * STAGE_B;
        const char* alo = ahi + PLANE_B;
        const char* bhi = alo + PLANE_B;
        const char* blo = bhi + PLANE_B;

#pragma unroll
        for (int ks = 0; ks < GBK; ks += 16) {
            uint32_t ah[4][4], al[4][4], bh[4][2], bl[4][2];
#pragma unroll
            for (int mt = 0; mt < 4; mt++) {
                int row = wm + mt * 16 + g;
                uint32_t o0 = row * (PADH * 2) + (ks + 2 * t) * 2;
                uint32_t o1 = (row + 8) * (PADH * 2) + (ks + 2 * t) * 2;
                ah[mt][0] = *(const uint32_t*)(ahi + o0);
                ah[mt][1] = *(const uint32_t*)(ahi + o1);
                ah[mt][2] = *(const uint32_t*)(ahi + o0 + 16);
                ah[mt][3] = *(const uint32_t*)(ahi + o1 + 16);
                al[mt][0] = *(const uint32_t*)(alo + o0);
                al[mt][1] = *(const uint32_t*)(alo + o1);
                al[mt][2] = *(const uint32_t*)(alo + o0 + 16);
                al[mt][3] = *(const uint32_t*)(alo + o1 + 16);
            }
#pragma unroll
            for (int ntl = 0; ntl < 4; ntl++) {
                int rn = wn + ntl * 8 + g;
                uint32_t ob = rn * (PADH * 2) + (ks + 2 * t) * 2;
                bh[ntl][0] = *(const uint32_t*)(bhi + ob);
                bh[ntl][1] = *(const uint32_t*)(bhi + ob + 16);
                bl[ntl][0] = *(const uint32_t*)(blo + ob);
                bl[ntl][1] = *(const uint32_t*)(blo + ob + 16);
            }
#pragma unroll
            for (int mt = 0; mt < 4; mt++)
#pragma unroll
                for (int ntl = 0; ntl < 4; ntl++) {
                    mma16816(acc[mt][ntl], ah[mt], bh[ntl]);
                    mma16816(acc[mt][ntl], ah[mt], bl[ntl]);
                    mma16816(acc[mt][ntl], al[mt], bh[ntl]);
                }
        }
        if (it + 1 < nt) STS((it + 1) & 1);
    }

    // epilogue
#pragma unroll
    for (int mt = 0; mt < 4; mt++)
#pragma unroll
        for (int ntl = 0; ntl < 4; ntl++) {
            int row = m0 + wm + mt * 16 + g;
            int col = n0 + wn + ntl * 8 + 2 * t;
            size_t i0 = (size_t)row * N + col;
            size_t i1 = (size_t)(row + 8) * N + col;
            float2 v0 = make_float2(acc[mt][ntl][0], acc[mt][ntl][1]);
            float2 v1 = make_float2(acc[mt][ntl][2], acc[mt][ntl][3]);
            if (ADD) {
                float2 c0 = *(const float2*)&C0[i0];
                float2 c1 = *(const float2*)&C0[i1];
                v0.x += c0.x; v0.y += c0.y; v1.x += c1.x; v1.y += c1.y;
            }
            if (RELU) {
                v0.x = fmaxf(v0.x, 0.f); v0.y = fmaxf(v0.y, 0.f);
                v1.x = fmaxf(v1.x, 0.f); v1.y = fmaxf(v1.y, 0.f);
            }
            *(float2*)&C[i0] = v0;
            *(float2*)&C[i1] = v1;
        }
}

// ---------------------------------------------------------------------------
// Scratch (single device global; no allocations anywhere)
// ---------------------------------------------------------------------------
#define WT_FLOATS (3 * E_ * E_ + 2 * E_ * FF_)
__device__ float g_scratch[(size_t)7 * BT_ * E_ + (size_t)BT_ * FF_ + WT_FLOATS];

// ---------------------------------------------------------------------------
// positional encoding add
// ---------------------------------------------------------------------------
__global__ void add_pos_kernel(const float4* __restrict__ q,
                               const float4* __restrict__ k,
                               const float4* __restrict__ pq,
                               const float4* __restrict__ pk,
                               float4* __restrict__ qin,
                               float4* __restrict__ kin) {
    int i  = blockIdx.x * 256 + threadIdx.x;
    int pi = i % (T_ * E_ / 4);
    const float s = 22.62741699796952f;
    float4 a = q[i], p = pq[pi];
    float4 r;
    r.x = a.x + p.x * s; r.y = a.y + p.y * s;
    r.z = a.z + p.z * s; r.w = a.w + p.w * s;
    qin[i] = r;
    a = k[i]; p = pk[pi];
    r.x = a.x + p.x * s; r.y = a.y + p.y * s;
    r.z = a.z + p.z * s; r.w = a.w + p.w * s;
    kin[i] = r;
}

// ---------------------------------------------------------------------------
// weight transpose  WT[n,k] = W[k,n]
// ---------------------------------------------------------------------------
__global__ void transpose_kernel(const float* __restrict__ W, float* __restrict__ WT,
                                 int K, int N) {
    __shared__ float t[32][33];
    int bn = blockIdx.x * 32, bk = blockIdx.y * 32;
    for (int j = threadIdx.y; j < 32; j += 8)
        t[j][threadIdx.x] = W[(size_t)(bk + j) * N + bn + threadIdx.x];
    __syncthreads();
    for (int j = threadIdx.y; j < 32; j += 8)
        WT[(size_t)(bn + j) * K + bk + threadIdx.x] = t[threadIdx.x][j];
}

// ---------------------------------------------------------------------------
// fused masked attention per (b,h)
// ---------------------------------------------------------------------------
__global__ void __launch_bounds__(256)
attn_kernel(const int* __restrict__ qlen, const int* __restrict__ klen,
            const float* __restrict__ Q, const float* __restrict__ Kt,
            const float* __restrict__ V, const float* __restrict__ qin,
            float* __restrict__ ctx) {
    extern __shared__ float sm[];
    float* Ks = sm;
    float* Vs = Ks + T_ * 65;
    float* Sc = Vs + T_ * 65;
    float* Qs = Sc + 8 * T_;

    const int h = blockIdx.x, b = blockIdx.y;
    const int tid = threadIdx.x, w = tid >> 5, lane = tid & 31;
    const int kl = klen[b], ql = qlen[b];

    for (int i = tid; i < T_ * DH_; i += 256) {
        int t = i >> 6, d = i & 63;
        size_t gi = (size_t)(b * T_ + t) * E_ + h * DH_ + d;
        Ks[t * 65 + d] = Kt[gi];
        Vs[t * 65 + d] = V[gi];
    }
    __syncthreads();

    const float inv_sqrt_dh = 0.125f;

    for (int q = w; q < T_; q += 8) {
        size_t qbase = (size_t)(b * T_ + q) * E_ + h * DH_;
        Qs[w * 64 + lane]      = Q[qbase + lane];
        Qs[w * 64 + lane + 32] = Q[qbase + lane + 32];
        __syncwarp();

        float smax = -INFINITY;
#pragma unroll
        for (int kb = 0; kb < 7; kb++) {
            int kk = kb * 32 + lane;
            if (kk < T_) {
                float dot = 0.f;
#pragma unroll
                for (int d = 0; d < DH_; d++)
                    dot += Qs[w * 64 + d] * Ks[kk * 65 + d];
                float s = (kk < kl && kk != q) ? dot * inv_sqrt_dh : NEGV;
                Sc[w * 200 + kk] = s;
                smax = fmaxf(smax, s);
            }
        }
#pragma unroll
        for (int off = 16; off; off >>= 1)
            smax = fmaxf(smax, __shfl_xor_sync(0xffffffff, smax, off));

        float ssum = 0.f;
#pragma unroll
        for (int kb = 0; kb < 7; kb++) {
            int kk = kb * 32 + lane;
            if (kk < T_) {
                float e = expf(Sc[w * 200 + kk] - smax);
                Sc[w * 200 + kk] = e;
                ssum += e;
            }
        }
#pragma unroll
        for (int off = 16; off; off >>= 1)
            ssum += __shfl_xor_sync(0xffffffff, ssum, off);

        float scale = (q < ql) ? (1.0f / ssum) : 0.0f;
        __syncwarp();

        float acc0 = 0.f, acc1 = 0.f;
        for (int kk = 0; kk < T_; kk++) {
            float p = Sc[w * 200 + kk];
            acc0 += p * Vs[kk * 65 + lane];
            acc1 += p * Vs[kk * 65 + lane + 32];
        }
        ctx[qbase + lane]      = acc0 * scale + qin[qbase + lane];
        ctx[qbase + lane + 32] = acc1 * scale + qin[qbase + lane + 32];
    }
}

// ---------------------------------------------------------------------------
// mean over T -> (B,1,E)
// ---------------------------------------------------------------------------
__global__ void mean_kernel(const float* __restrict__ o2, float* __restrict__ out) {
    int b = blockIdx.x, e = threadIdx.x;
    float s = 0.f;
    for (int t = 0; t < T_; t++)
        s += o2[(size_t)(b * T_ + t) * E_ + e];
    out[b * E_ + e] = s * (1.0f / T_);
}

// ---------------------------------------------------------------------------
// Launch
// ---------------------------------------------------------------------------
extern "C" void kernel_launch(void* const* d_in, const int* in_sizes, int n_in,
                              void* d_out, int out_size) {
    const float* queries = (const float*)d_in[0];
    const float* keys    = (const float*)d_in[1];
    const int*   qlen    = (const int*)d_in[2];
    const int*   klen    = (const int*)d_in[3];
    const float* pos_q   = (const float*)d_in[4];
    const float* pos_k   = (const float*)d_in[5];
    const float* W_Q     = (const float*)d_in[6];
    const float* W_K     = (const float*)d_in[7];
    const float* W_V     = (const float*)d_in[8];
    const float* fw1     = (const float*)d_in[9];
    const float* fw2     = (const float*)d_in[10];
    float*       out     = (float*)d_out;

    float* base = nullptr;
    cudaGetSymbolAddress((void**)&base, g_scratch);
    const size_t BTE = (size_t)BT_ * E_;
    float* qin = base;
    float* kin = base + 1 * BTE;
    float* Qp  = base + 2 * BTE;
    float* Kp  = base + 3 * BTE;
    float* Vp  = base + 4 * BTE;
    float* ctx = base + 5 * BTE;
    float* o2  = base + 6 * BTE;
    float* hid = base + 7 * BTE;
    float* wqT = hid + (size_t)BT_ * FF_;
    float* wkT = wqT + E_ * E_;
    float* wvT = wkT + E_ * E_;
    float* f1T = wvT + E_ * E_;
    float* f2T = f1T + (size_t)E_ * FF_;

    cudaFuncSetAttribute(hgemm_kernel<false, false>,
                         cudaFuncAttributeMaxDynamicSharedMemorySize, GEMM_DSMEM);
    cudaFuncSetAttribute(hgemm_kernel<true, false>,
                         cudaFuncAttributeMaxDynamicSharedMemorySize, GEMM_DSMEM);
    cudaFuncSetAttribute(hgemm_kernel<false, true>,
                         cudaFuncAttributeMaxDynamicSharedMemorySize, GEMM_DSMEM);
    const int SMEM_ATT = (2 * T_ * 65 + 8 * T_ + 8 * 64) * (int)sizeof(float);
    cudaFuncSetAttribute(attn_kernel,
                         cudaFuncAttributeMaxDynamicSharedMemorySize, SMEM_ATT);

    // 1. positional encoding
    add_pos_kernel<<<(BT_ * E_ / 4) / 256, 256>>>(
        (const float4*)queries, (const float4*)keys,
        (const float4*)pos_q, (const float4*)pos_k,
        (float4*)qin, (float4*)kin);

    // 2. weight transposes (K-major B operands)
    dim3 tb(32, 8);
    transpose_kernel<<<dim3(E_ / 32, E_ / 32), tb>>>(W_Q, wqT, E_, E_);
    transpose_kernel<<<dim3(E_ / 32, E_ / 32), tb>>>(W_K, wkT, E_, E_);
    transpose_kernel<<<dim3(E_ / 32, E_ / 32), tb>>>(W_V, wvT, E_, E_);
    transpose_kernel<<<dim3(FF_ / 32, E_ / 32), tb>>>(fw1, f1T, E_, FF_);
    transpose_kernel<<<dim3(E_ / 32, FF_ / 32), tb>>>(fw2, f2T, FF_, E_);

    // 3. QKV projections (tensor-core fp16-split)
    dim3 gproj(E_ / GBN, BT_ / GBM);
    hgemm_kernel<false, false><<<gproj, 256, GEMM_DSMEM>>>(qin, wqT, nullptr, Qp, BT_, E_, E_);
    hgemm_kernel<false, false><<<gproj, 256, GEMM_DSMEM>>>(kin, wkT, nullptr, Kp, BT_, E_, E_);
    hgemm_kernel<false, false><<<gproj, 256, GEMM_DSMEM>>>(kin, wvT, nullptr, Vp, BT_, E_, E_);

    // 4. fused attention (+ residual)
    attn_kernel<<<dim3(H_, B_), 256, SMEM_ATT>>>(qlen, klen, Qp, Kp, Vp, qin, ctx);

    // 5. FFN up + ReLU
    hgemm_kernel<true, false><<<dim3(FF_ / GBN, BT_ / GBM), 256, GEMM_DSMEM>>>(
        ctx, f1T, nullptr, hid, BT_, FF_, E_);

    // 6. FFN down + residual
    hgemm_kernel<false, true><<<dim3(E_ / GBN, BT_ / GBM), 256, GEMM_DSMEM>>>(
        hid, f2T, ctx, o2, BT_, E_, FF_);

    // 7. mean over time
    mean_kernel<<<B_, E_>>>(o2, out);
}

// round 4
// speedup vs baseline: 1.9442x; 1.1957x over previous
#include <cuda_runtime.h>
#include <cuda_fp16.h>
#include <math.h>
#include <stdint.h>

// Problem dims
#define B_   256
#define T_   200
#define E_   512
#define H_   8
#define DH_  64
#define FF_  2048
#define BT_  (B_*T_)

#define NEGV (-4294967295.0f)

// ---------------------------------------------------------------------------
// GEMM config: 128x128 CTA tile, BK=32, 8 warps (2x4), warp tile 64x32.
// ---------------------------------------------------------------------------
#define GBM 128
#define GBN 128
#define GBK 32
#define PADH 40
#define PLANE_B (GBM * PADH * 2)
#define STAGE_B (4 * PLANE_B)
#define GEMM_DSMEM (2 * STAGE_B)

__device__ __forceinline__ void mma16816(float* c, const uint32_t* a, const uint32_t* b) {
    asm volatile(
        "mma.sync.aligned.m16n8k16.row.col.f32.f16.f16.f32 "
        "{%0,%1,%2,%3}, {%4,%5,%6,%7}, {%8,%9}, {%0,%1,%2,%3};"
        : "+f"(c[0]), "+f"(c[1]), "+f"(c[2]), "+f"(c[3])
        : "r"(a[0]), "r"(a[1]), "r"(a[2]), "r"(a[3]), "r"(b[0]), "r"(b[1]));
}

__device__ __forceinline__ void split2(float x, float y, uint32_t& hi, uint32_t& lo) {
    __half hx = __float2half_rn(x);
    __half hy = __float2half_rn(y);
    __half lx = __float2half_rn(x - __half2float(hx));
    __half ly = __float2half_rn(y - __half2float(hy));
    hi = (uint32_t)__half_as_ushort(hx) | ((uint32_t)__half_as_ushort(hy) << 16);
    lo = (uint32_t)__half_as_ushort(lx) | ((uint32_t)__half_as_ushort(ly) << 16);
}

template <bool RELU, bool ADD>
__global__ void __launch_bounds__(256)
hgemm_kernel(const float* __restrict__ A, const float* __restrict__ Bt,
             const float* __restrict__ C0, float* __restrict__ C,
             int M, int N, int K) {
    extern __shared__ char smem[];

    const int tid = threadIdx.x;
    const int wid = tid >> 5, lane = tid & 31;
    const int m0 = blockIdx.y * GBM;
    const int n0 = blockIdx.x * GBN;
    const int wm = (wid >> 2) * 64;
    const int wn = (wid & 3) * 32;
    const int g = lane >> 2, t = lane & 3;

    float acc[4][4][4];
#pragma unroll
    for (int i = 0; i < 4; i++)
#pragma unroll
        for (int j = 0; j < 4; j++)
#pragma unroll
            for (int k = 0; k < 4; k++) acc[i][j][k] = 0.f;

    const int nt = K / GBK;
    float4 la[4], lb[4];

    auto LDG = [&](int k0) {
#pragma unroll
        for (int j = 0; j < 4; j++) {
            int f4 = tid + j * 256;
            int r = f4 >> 3, c4 = f4 & 7;
            la[j] = *(const float4*)(A + (size_t)(m0 + r) * K + k0 + c4 * 4);
            lb[j] = *(const float4*)(Bt + (size_t)(n0 + r) * K + k0 + c4 * 4);
        }
    };
    auto STS = [&](int s) {
        char* ahi = smem + s * STAGE_B;
        char* alo = ahi + PLANE_B;
        char* bhi = alo + PLANE_B;
        char* blo = bhi + PLANE_B;
#pragma unroll
        for (int j = 0; j < 4; j++) {
            int f4 = tid + j * 256;
            int r = f4 >> 3, c4 = f4 & 7;
            uint32_t off = r * (PADH * 2) + c4 * 8;
            uint32_t h01, l01, h23, l23;
            split2(la[j].x, la[j].y, h01, l01);
            split2(la[j].z, la[j].w, h23, l23);
            *(uint2*)(ahi + off) = make_uint2(h01, h23);
            *(uint2*)(alo + off) = make_uint2(l01, l23);
            split2(lb[j].x, lb[j].y, h01, l01);
            split2(lb[j].z, lb[j].w, h23, l23);
            *(uint2*)(bhi + off) = make_uint2(h01, h23);
            *(uint2*)(blo + off) = make_uint2(l01, l23);
        }
    };

    LDG(0);
    STS(0);

    for (int it = 0; it < nt; it++) {
        __syncthreads();
        if (it + 1 < nt) LDG((it + 1) * GBK);

        const char* ahi = smem + (it & 1) * STAGE_B;
        const char* alo = ahi + PLANE_B;
        const char* bhi = alo + PLANE_B;
        const char* blo = bhi + PLANE_B;

#pragma unroll
        for (int ks = 0; ks < GBK; ks += 16) {
            uint32_t ah[4][4], al[4][4], bh[4][2], bl[4][2];
#pragma unroll
            for (int mt = 0; mt < 4; mt++) {
                int row = wm + mt * 16 + g;
                uint32_t o0 = row * (PADH * 2) + (ks + 2 * t) * 2;
                uint32_t o1 = (row + 8) * (PADH * 2) + (ks + 2 * t) * 2;
                ah[mt][0] = *(const uint32_t*)(ahi + o0);
                ah[mt][1] = *(const uint32_t*)(ahi + o1);
                ah[mt][2] = *(const uint32_t*)(ahi + o0 + 16);
                ah[mt][3] = *(const uint32_t*)(ahi + o1 + 16);
                al[mt][0] = *(const uint32_t*)(alo + o0);
                al[mt][1] = *(const uint32_t*)(alo + o1);
                al[mt][2] = *(const uint32_t*)(alo + o0 + 16);
                al[mt][3] = *(const uint32_t*)(alo + o1 + 16);
            }
#pragma unroll
            for (int ntl = 0; ntl < 4; ntl++) {
                int rn = wn + ntl * 8 + g;
                uint32_t ob = rn * (PADH * 2) + (ks + 2 * t) * 2;
                bh[ntl][0] = *(const uint32_t*)(bhi + ob);
                bh[ntl][1] = *(const uint32_t*)(bhi + ob + 16);
                bl[ntl][0] = *(const uint32_t*)(blo + ob);
                bl[ntl][1] = *(const uint32_t*)(blo + ob + 16);
            }
#pragma unroll
            for (int mt = 0; mt < 4; mt++)
#pragma unroll
                for (int ntl = 0; ntl < 4; ntl++) {
                    mma16816(acc[mt][ntl], ah[mt], bh[ntl]);
                    mma16816(acc[mt][ntl], ah[mt], bl[ntl]);
                    mma16816(acc[mt][ntl], al[mt], bh[ntl]);
                }
        }
        if (it + 1 < nt) STS((it + 1) & 1);
    }

#pragma unroll
    for (int mt = 0; mt < 4; mt++)
#pragma unroll
        for (int ntl = 0; ntl < 4; ntl++) {
            int row = m0 + wm + mt * 16 + g;
            int col = n0 + wn + ntl * 8 + 2 * t;
            size_t i0 = (size_t)row * N + col;
            size_t i1 = (size_t)(row + 8) * N + col;
            float2 v0 = make_float2(acc[mt][ntl][0], acc[mt][ntl][1]);
            float2 v1 = make_float2(acc[mt][ntl][2], acc[mt][ntl][3]);
            if (ADD) {
                float2 c0 = *(const float2*)&C0[i0];
                float2 c1 = *(const float2*)&C0[i1];
                v0.x += c0.x; v0.y += c0.y; v1.x += c1.x; v1.y += c1.y;
            }
            if (RELU) {
                v0.x = fmaxf(v0.x, 0.f); v0.y = fmaxf(v0.y, 0.f);
                v1.x = fmaxf(v1.x, 0.f); v1.y = fmaxf(v1.y, 0.f);
            }
            *(float2*)&C[i0] = v0;
            *(float2*)&C[i1] = v1;
        }
}

// ---------------------------------------------------------------------------
// Scratch
// ---------------------------------------------------------------------------
#define WT_FLOATS (3 * E_ * E_ + 2 * E_ * FF_)
__device__ float g_scratch[(size_t)7 * BT_ * E_ + (size_t)BT_ * FF_ + WT_FLOATS];

// ---------------------------------------------------------------------------
// positional encoding add
// ---------------------------------------------------------------------------
__global__ void add_pos_kernel(const float4* __restrict__ q,
                               const float4* __restrict__ k,
                               const float4* __restrict__ pq,
                               const float4* __restrict__ pk,
                               float4* __restrict__ qin,
                               float4* __restrict__ kin) {
    int i  = blockIdx.x * 256 + threadIdx.x;
    int pi = i % (T_ * E_ / 4);
    const float s = 22.62741699796952f;
    float4 a = q[i], p = pq[pi];
    float4 r;
    r.x = a.x + p.x * s; r.y = a.y + p.y * s;
    r.z = a.z + p.z * s; r.w = a.w + p.w * s;
    qin[i] = r;
    a = k[i]; p = pk[pi];
    r.x = a.x + p.x * s; r.y = a.y + p.y * s;
    r.z = a.z + p.z * s; r.w = a.w + p.w * s;
    kin[i] = r;
}

// ---------------------------------------------------------------------------
// all 5 weight transposes in ONE launch.  WT[n,k] = W[k,n]
// tiles: WQ/WK/WV 256 each, fw1 1024, fw2 1024  (total 2816 blocks)
// ---------------------------------------------------------------------------
__global__ void transpose_all_kernel(
    const float* __restrict__ WQ, const float* __restrict__ WK,
    const float* __restrict__ WV, const float* __restrict__ F1,
    const float* __restrict__ F2,
    float* __restrict__ wqT, float* __restrict__ wkT, float* __restrict__ wvT,
    float* __restrict__ f1T, float* __restrict__ f2T) {
    __shared__ float t[32][33];
    int bid = blockIdx.x;
    const float* W; float* WT; int K, N, tile;
    if (bid < 256)       { W = WQ; WT = wqT; K = E_;  N = E_;  tile = bid; }
    else if (bid < 512)  { W = WK; WT = wkT; K = E_;  N = E_;  tile = bid - 256; }
    else if (bid < 768)  { W = WV; WT = wvT; K = E_;  N = E_;  tile = bid - 512; }
    else if (bid < 1792) { W = F1; WT = f1T; K = E_;  N = FF_; tile = bid - 768; }
    else                 { W = F2; WT = f2T; K = FF_; N = E_;  tile = bid - 1792; }
    int ntx = N / 32;
    int bn = (tile % ntx) * 32, bk = (tile / ntx) * 32;
    for (int j = threadIdx.y; j < 32; j += 8)
        t[j][threadIdx.x] = W[(size_t)(bk + j) * N + bn + threadIdx.x];
    __syncthreads();
    for (int j = threadIdx.y; j < 32; j += 8)
        WT[(size_t)(bn + j) * K + bk + threadIdx.x] = t[threadIdx.x][j];
}

// ---------------------------------------------------------------------------
// fused masked attention per (b,h) — v2: 4 q-rows per warp pass, float4 K
// reads (stride 68 = 16B aligned, conflict-free), __expf, masked-chunk skip.
// KV is the merged buffer [BT][1024]: K at cols 0..511, V at 512..1023.
// ---------------------------------------------------------------------------
#define ATS 68
__global__ void __launch_bounds__(256)
attn_kernel(const int* __restrict__ qlen, const int* __restrict__ klen,
            const float* __restrict__ Q, const float* __restrict__ KV,
            const float* __restrict__ qin, float* __restrict__ ctx) {
    extern __shared__ float sm[];
    float* Ks = sm;                     // 200*68
    float* Vs = Ks + T_ * ATS;          // 200*68
    float* Sc = Vs + T_ * ATS;          // 32*200
    float* Qs = Sc + 32 * T_;           // 32*64

    const int h = blockIdx.x, b = blockIdx.y;
    const int tid = threadIdx.x, w = tid >> 5, lane = tid & 31;
    const int kl = klen[b], ql = qlen[b];
    const int kbmax = (kl + 31) >> 5;   // chunks containing any valid key (>=1)

    // load K,V head tiles
    for (int i = tid; i < T_ * 16; i += 256) {
        int t = i >> 4, d4 = (i & 15) * 4;
        size_t gk = (size_t)(b * T_ + t) * 1024 + h * DH_ + d4;
        *(float4*)&Ks[t * ATS + d4] = *(const float4*)&KV[gk];
        *(float4*)&Vs[t * ATS + d4] = *(const float4*)&KV[gk + 512];
    }
    __syncthreads();

    for (int bi = w; bi * 4 < T_; bi += 8) {
        const int qq0 = bi * 4;
        const int w4 = w * 4;

        // load 4 Q rows into smem (per-warp region)
#pragma unroll
        for (int j = 0; j < 2; j++) {
            int f4 = lane + j * 32;
            int r = f4 >> 4, d4 = (f4 & 15) * 4;
            *(float4*)&Qs[(w4 + r) * 64 + d4] =
                *(const float4*)&Q[(size_t)(b * T_ + qq0 + r) * E_ + h * DH_ + d4];
        }
        __syncwarp();

        // ---- scores for valid chunks, track rowmax ----
        float mx[4] = {-INFINITY, -INFINITY, -INFINITY, -INFINITY};
        for (int kb = 0; kb < kbmax; kb++) {
            int kk = kb * 32 + lane;
            if (kk < T_) {
                float a0 = 0.f, a1 = 0.f, a2 = 0.f, a3 = 0.f;
                const float* kr = &Ks[kk * ATS];
                const float* q0 = &Qs[(w4 + 0) * 64];
                const float* q1 = &Qs[(w4 + 1) * 64];
                const float* q2 = &Qs[(w4 + 2) * 64];
                const float* q3 = &Qs[(w4 + 3) * 64];
#pragma unroll
                for (int d = 0; d < DH_; d += 4) {
                    float4 kv = *(const float4*)&kr[d];
                    float4 qa = *(const float4*)&q0[d];
                    a0 += kv.x * qa.x + kv.y * qa.y + kv.z * qa.z + kv.w * qa.w;
                    qa = *(const float4*)&q1[d];
                    a1 += kv.x * qa.x + kv.y * qa.y + kv.z * qa.z + kv.w * qa.w;
                    qa = *(const float4*)&q2[d];
                    a2 += kv.x * qa.x + kv.y * qa.y + kv.z * qa.z + kv.w * qa.w;
                    qa = *(const float4*)&q3[d];
                    a3 += kv.x * qa.x + kv.y * qa.y + kv.z * qa.z + kv.w * qa.w;
                }
                float sv[4] = {a0, a1, a2, a3};
#pragma unroll
                for (int r = 0; r < 4; r++) {
                    float s = (kk < kl && kk != qq0 + r) ? sv[r] * 0.125f : NEGV;
                    Sc[(w4 + r) * T_ + kk] = s;
                    mx[r] = fmaxf(mx[r], s);
                }
            }
        }
#pragma unroll
        for (int r = 0; r < 4; r++)
#pragma unroll
            for (int off = 16; off; off >>= 1)
                mx[r] = fmaxf(mx[r], __shfl_xor_sync(0xffffffff, mx[r], off));

        // ---- exp + rowsum ----
        float sum[4] = {0.f, 0.f, 0.f, 0.f};
        for (int kb = 0; kb < kbmax; kb++) {
            int kk = kb * 32 + lane;
            if (kk < T_) {
#pragma unroll
                for (int r = 0; r < 4; r++) {
                    float e = __expf(Sc[(w4 + r) * T_ + kk] - mx[r]);
                    Sc[(w4 + r) * T_ + kk] = e;
                    sum[r] += e;
                }
            }
        }
        // all-masked rows (mx == NEGV): reference gives uniform softmax over all
        // T_ keys. Fill remaining chunks (1 for am-rows, 0 for others).
        bool am[4];
        bool any_am = false;
#pragma unroll
        for (int r = 0; r < 4; r++) { am[r] = (mx[r] == NEGV); any_am |= am[r]; }
        if (any_am) {
            for (int kb = kbmax; kb < 7; kb++) {
                int kk = kb * 32 + lane;
                if (kk < T_) {
#pragma unroll
                    for (int r = 0; r < 4; r++) {
                        float v = am[r] ? 1.f : 0.f;
                        Sc[(w4 + r) * T_ + kk] = v;
                        sum[r] += v;
                    }
                }
            }
        }
#pragma unroll
        for (int r = 0; r < 4; r++)
#pragma unroll
            for (int off = 16; off; off >>= 1)
                sum[r] += __shfl_xor_sync(0xffffffff, sum[r], off);

        float inv[4];
#pragma unroll
        for (int r = 0; r < 4; r++)
            inv[r] = (qq0 + r < ql) ? (1.0f / sum[r]) : 0.0f;
        __syncwarp();

        // ---- attn @ V (lane owns dims lane, lane+32) ----
        int kku = any_am ? T_ : min(kbmax * 32, T_);
        float o0[4] = {0.f, 0.f, 0.f, 0.f};
        float o1[4] = {0.f, 0.f, 0.f, 0.f};
        for (int kk = 0; kk < kku; kk++) {
            float v0 = Vs[kk * ATS + lane];
            float v1 = Vs[kk * ATS + lane + 32];
#pragma unroll
            for (int r = 0; r < 4; r++) {
                float p = Sc[(w4 + r) * T_ + kk];
                o0[r] += p * v0;
                o1[r] += p * v1;
            }
        }
#pragma unroll
        for (int r = 0; r < 4; r++) {
            size_t qb = (size_t)(b * T_ + qq0 + r) * E_ + h * DH_;
            ctx[qb + lane]      = o0[r] * inv[r] + qin[qb + lane];
            ctx[qb + lane + 32] = o1[r] * inv[r] + qin[qb + lane + 32];
        }
        __syncwarp();
    }
}

// ---------------------------------------------------------------------------
// mean over T -> (B,1,E)
// ---------------------------------------------------------------------------
__global__ void mean_kernel(const float* __restrict__ o2, float* __restrict__ out) {
    int b = blockIdx.x, e = threadIdx.x;
    float s = 0.f;
    for (int t = 0; t < T_; t++)
        s += o2[(size_t)(b * T_ + t) * E_ + e];
    out[b * E_ + e] = s * (1.0f / T_);
}

// ---------------------------------------------------------------------------
// Launch.  Order puts FFN1 GEMM at launch #6 so ncu -s 5 -c 1 profiles it.
// ---------------------------------------------------------------------------
extern "C" void kernel_launch(void* const* d_in, const int* in_sizes, int n_in,
                              void* d_out, int out_size) {
    const float* queries = (const float*)d_in[0];
    const float* keys    = (const float*)d_in[1];
    const int*   qlen    = (const int*)d_in[2];
    const int*   klen    = (const int*)d_in[3];
    const float* pos_q   = (const float*)d_in[4];
    const float* pos_k   = (const float*)d_in[5];
    const float* W_Q     = (const float*)d_in[6];
    const float* W_K     = (const float*)d_in[7];
    const float* W_V     = (const float*)d_in[8];
    const float* fw1     = (const float*)d_in[9];
    const float* fw2     = (const float*)d_in[10];
    float*       out     = (float*)d_out;

    float* base = nullptr;
    cudaGetSymbolAddress((void**)&base, g_scratch);
    const size_t BTE = (size_t)BT_ * E_;
    float* qin = base;
    float* kin = base + 1 * BTE;
    float* Qp  = base + 2 * BTE;
    float* KVb = base + 3 * BTE;            // merged [BT][1024]
    float* ctx = base + 5 * BTE;
    float* o2  = base + 6 * BTE;
    float* hid = base + 7 * BTE;
    float* wqT = hid + (size_t)BT_ * FF_;
    float* wkT = wqT + E_ * E_;             // wkT,wvT adjacent = [1024][512]
    float* wvT = wkT + E_ * E_;
    float* f1T = wvT + E_ * E_;
    float* f2T = f1T + (size_t)E_ * FF_;

    cudaFuncSetAttribute(hgemm_kernel<false, false>,
                         cudaFuncAttributeMaxDynamicSharedMemorySize, GEMM_DSMEM);
    cudaFuncSetAttribute(hgemm_kernel<true, false>,
                         cudaFuncAttributeMaxDynamicSharedMemorySize, GEMM_DSMEM);
    cudaFuncSetAttribute(hgemm_kernel<false, true>,
                         cudaFuncAttributeMaxDynamicSharedMemorySize, GEMM_DSMEM);
    const int SMEM_ATT = (2 * T_ * ATS + 32 * T_ + 32 * 64) * (int)sizeof(float);
    cudaFuncSetAttribute(attn_kernel,
                         cudaFuncAttributeMaxDynamicSharedMemorySize, SMEM_ATT);

    // 1. all weight transposes
    transpose_all_kernel<<<2816, dim3(32, 8)>>>(W_Q, W_K, W_V, fw1, fw2,
                                                wqT, wkT, wvT, f1T, f2T);
    // 2. positional encoding
    add_pos_kernel<<<(BT_ * E_ / 4) / 256, 256>>>(
        (const float4*)queries, (const float4*)keys,
        (const float4*)pos_q, (const float4*)pos_k,
        (float4*)qin, (float4*)kin);

    // 3. Q projection
    hgemm_kernel<false, false><<<dim3(E_ / GBN, BT_ / GBM), 256, GEMM_DSMEM>>>(
        qin, wqT, nullptr, Qp, BT_, E_, E_);
    // 4. merged K+V projection -> KVb [BT][1024]
    hgemm_kernel<false, false><<<dim3(2 * E_ / GBN, BT_ / GBM), 256, GEMM_DSMEM>>>(
        kin, wkT, nullptr, KVb, BT_, 2 * E_, E_);

    // 5. fused attention (+ residual)
    attn_kernel<<<dim3(H_, B_), 256, SMEM_ATT>>>(qlen, klen, Qp, KVb, qin, ctx);

    // 6. FFN up + ReLU   <-- profiled by ncu (-s 5 -c 1)
    hgemm_kernel<true, false><<<dim3(FF_ / GBN, BT_ / GBM), 256, GEMM_DSMEM>>>(
        ctx, f1T, nullptr, hid, BT_, FF_, E_);

    // 7. FFN down + residual
    hgemm_kernel<false, true><<<dim3(E_ / GBN, BT_ / GBM), 256, GEMM_DSMEM>>>(
        hid, f2T, ctx, o2, BT_, E_, FF_);

    // 8. mean over time
    mean_kernel<<<B_, E_>>>(o2, out);
}